// round 17
// baseline (speedup 1.0000x reference)
#include <cuda_runtime.h>
#include <cstdint>

#define B_POINTS 131072
#define NSTEP    64
#define NTHREADS 128
#define NBLOCKS  (B_POINTS / NTHREADS)   // 1024

typedef unsigned long long u64;

// ---- f32x2 packed helpers (sm_103a FFMA2 path, PTX-only) ----
__device__ __forceinline__ u64 f2fma(u64 a, u64 b, u64 c) {
    u64 d;
    asm("fma.rn.f32x2 %0, %1, %2, %3;" : "=l"(d) : "l"(a), "l"(b), "l"(c));
    return d;
}
__device__ __forceinline__ u64 pack2(float lo, float hi) {
    u64 d;
    asm("mov.b64 %0, {%1, %2};" : "=l"(d) : "f"(lo), "f"(hi));
    return d;
}
__device__ __forceinline__ void unpack2(u64 v, float& lo, float& hi) {
    asm("mov.b64 {%0, %1}, %2;" : "=f"(lo), "=f"(hi) : "l"(v));
}
__device__ __forceinline__ u64 f2relu(u64 v) {
    float lo, hi;
    unpack2(v, lo, hi);
    return pack2(fmaxf(lo, 0.0f), fmaxf(hi, 0.0f));   // FMNMX = alu pipe
}

// ---- ALL weights in constant: uniform LDCU port, zero smem-crossbar traffic ----
struct CW {
    ulonglong2 w2v[32 * 8];   // [i*8+q] = floats w2[i][4q..4q+3]  (full row, 32 outputs)
    u64        w1p[64];       // [m*4+d] = (w1[d][2m], w1[d][2m+1]); d=3 -> (b1[2m], b1[2m+1])
    u64        w3p[48];       // [o*16+m] = (w3[2m][o], w3[2m+1][o])
    u64        b2p[16];       // (b2[2m], b2[2m+1])
    float      b3s[3];
    float      wo[4];         // w_out[0..2], b_out
};
__device__   CW g_stage;
__constant__ CW cw;

__global__ void prep_kernel(const float* __restrict__ w1, const float* __restrict__ b1,
                            const float* __restrict__ w2, const float* __restrict__ b2,
                            const float* __restrict__ w3, const float* __restrict__ b3,
                            const float* __restrict__ w_out, const float* __restrict__ b_out)
{
    const int t = threadIdx.x;   // 128 threads
    for (int i = t; i < 1024; i += 128)
        ((float*)g_stage.w2v)[i] = w2[i];
    if (t < 16) {
        g_stage.w1p[t * 4 + 0] = pack2(w1[0 * 32 + 2 * t], w1[0 * 32 + 2 * t + 1]);
        g_stage.w1p[t * 4 + 1] = pack2(w1[1 * 32 + 2 * t], w1[1 * 32 + 2 * t + 1]);
        g_stage.w1p[t * 4 + 2] = pack2(w1[2 * 32 + 2 * t], w1[2 * 32 + 2 * t + 1]);
        g_stage.w1p[t * 4 + 3] = pack2(b1[2 * t], b1[2 * t + 1]);
        g_stage.b2p[t] = pack2(b2[2 * t], b2[2 * t + 1]);
    }
    if (t >= 32 && t < 80) {
        int i = t - 32, o = i / 16, m = i % 16;
        g_stage.w3p[o * 16 + m] = pack2(w3[(2 * m) * 3 + o], w3[(2 * m + 1) * 3 + o]);
    }
    if (t >= 80 && t < 83) { g_stage.b3s[t - 80] = b3[t - 80]; g_stage.wo[t - 80] = w_out[t - 80]; }
    if (t == 83) g_stage.wo[3] = b_out[0];
}

__global__ __launch_bounds__(NTHREADS, 6)   // 85-reg budget; avoids forced spills
void ode_rk4_kernel(const float* __restrict__ x,
                    const float* __restrict__ samples,
                    float* __restrict__ out)
{
    __shared__ float sdt;
    __shared__ int   ssidx[8];

    const int t = threadIdx.x;

    if (t == 0) {
        float mx = samples[0];
        #pragma unroll
        for (int s = 1; s < 8; s++) mx = fmaxf(mx, samples[s]);
        sdt = mx / (float)NSTEP;
    }
    __syncthreads();
    if (t < 8) {
        int ii = (int)(rintf(samples[t] / sdt)) - 1;
        ssidx[t] = min(max(ii, 0), NSTEP - 1);
    }
    __syncthreads();

    u64 emit_mask = 0ull;
    #pragma unroll
    for (int s = 0; s < 8; s++) emit_mask |= 1ull << ssidx[s];

    const float dt  = sdt;
    const float hdt = 0.5f * dt;
    const float sx  = dt / 6.0f;
    const float bq0 = cw.b3s[0], bq1 = cw.b3s[1], bq2 = cw.b3s[2];

    const int p = blockIdx.x * NTHREADS + t;   // 1 point per thread
    float y0 = x[p * 3 + 0], y1 = x[p * 3 + 1], y2 = x[p * 3 + 2];

    // MLP 3->32->32->3 for ONE point; all weights via the uniform constant port.
    auto mlp = [&](float a0, float a1, float a2,
                   float& k0, float& k1, float& k2) {
        u64 ad0 = pack2(a0, a0), ad1 = pack2(a1, a1), ad2 = pack2(a2, a2);
        u64 h[16];
        #pragma unroll
        for (int m = 0; m < 16; m++) h[m] = cw.b2p[m];
        #pragma unroll 4
        for (int m = 0; m < 16; m++) {       // layer-1 neuron pair (2m, 2m+1)
            u64 hp = f2fma(ad2, cw.w1p[m * 4 + 2], cw.w1p[m * 4 + 3]);
            hp = f2fma(ad1, cw.w1p[m * 4 + 1], hp);
            hp = f2fma(ad0, cw.w1p[m * 4 + 0], hp);
            float e0, e1;
            unpack2(hp, e0, e1);
            e0 = fmaxf(e0, 0.0f);
            e1 = fmaxf(e1, 0.0f);
            u64 d0 = pack2(e0, e0), d1 = pack2(e1, e1);
            #pragma unroll
            for (int q = 0; q < 8; q++) {    // neuron i = 2m: full 32-output row
                ulonglong2 w = cw.w2v[(2 * m) * 8 + q];
                h[2 * q]     = f2fma(d0, w.x, h[2 * q]);
                h[2 * q + 1] = f2fma(d0, w.y, h[2 * q + 1]);
            }
            #pragma unroll
            for (int q = 0; q < 8; q++) {    // neuron i = 2m+1
                ulonglong2 w = cw.w2v[(2 * m + 1) * 8 + q];
                h[2 * q]     = f2fma(d1, w.x, h[2 * q]);
                h[2 * q + 1] = f2fma(d1, w.y, h[2 * q + 1]);
            }
        }
        u64 z = pack2(0.0f, 0.0f);
        u64 c0 = z, c1 = z, c2 = z;
        #pragma unroll
        for (int m = 0; m < 16; m++) {
            u64 r = f2relu(h[m]);
            c0 = f2fma(r, cw.w3p[m],      c0);
            c1 = f2fma(r, cw.w3p[16 + m], c1);
            c2 = f2fma(r, cw.w3p[32 + m], c2);
        }
        float lo, hi;
        unpack2(c0, lo, hi); k0 = bq0 + lo + hi;
        unpack2(c1, lo, hi); k1 = bq1 + lo + hi;
        unpack2(c2, lo, hi); k2 = bq2 + lo + hi;
    };

    #pragma unroll 1
    for (int step = 0; step < NSTEP; step++) {
        float s0 = 0.f, s1 = 0.f, s2 = 0.f;
        float a0 = y0, a1 = y1, a2 = y2;

        #pragma unroll 1
        for (int st = 0; st < 4; st++) {
            float k0, k1, k2;
            mlp(a0, a1, a2, k0, k1, k2);
            float cs = (st == 1 || st == 2) ? 2.0f : 1.0f;
            float ca = (st == 2) ? dt : hdt;
            s0 = fmaf(k0, cs, s0); s1 = fmaf(k1, cs, s1); s2 = fmaf(k2, cs, s2);
            a0 = fmaf(k0, ca, y0); a1 = fmaf(k1, ca, y1); a2 = fmaf(k2, ca, y2);
        }
        y0 = fmaf(s0, sx, y0); y1 = fmaf(s1, sx, y1); y2 = fmaf(s2, sx, y2);

        if ((emit_mask >> step) & 1ull) {
            float o = fmaf(y0, cw.wo[0], fmaf(y1, cw.wo[1], fmaf(y2, cw.wo[2], cw.wo[3])));
            #pragma unroll 1
            for (int s = 0; s < 8; s++) {
                if (ssidx[s] == step) out[s * B_POINTS + p] = o;
            }
        }
    }
}

extern "C" void kernel_launch(void* const* d_in, const int* in_sizes, int n_in,
                              void* d_out, int out_size)
{
    const float* x      = (const float*)d_in[0];
    const float* samples= (const float*)d_in[1];
    const float* w1     = (const float*)d_in[2];
    const float* b1     = (const float*)d_in[3];
    const float* w2     = (const float*)d_in[4];
    const float* b2     = (const float*)d_in[5];
    const float* w3     = (const float*)d_in[6];
    const float* b3     = (const float*)d_in[7];
    const float* w_out  = (const float*)d_in[8];
    const float* b_out  = (const float*)d_in[9];
    float* out = (float*)d_out;

    // Stage transformed weights, then copy into __constant__ (D2D, capturable).
    prep_kernel<<<1, 128>>>(w1, b1, w2, b2, w3, b3, w_out, b_out);
    void* stage_addr = nullptr;
    cudaGetSymbolAddress(&stage_addr, g_stage);
    cudaMemcpyToSymbolAsync(cw, stage_addr, sizeof(CW), 0,
                            cudaMemcpyDeviceToDevice, 0);

    ode_rk4_kernel<<<NBLOCKS, NTHREADS>>>(x, samples, out);
}